// round 14
// baseline (speedup 1.0000x reference)
#include <cuda_runtime.h>
#include <cuda_bf16.h>
#include <cstdint>

// ====================== mma.sync helpers ======================
__device__ __forceinline__ uint32_t smem_to_u32(const void* smem_ptr) {
    uint32_t addr;
    asm("{ .reg .u64 tmp; cvta.to.shared.u64 tmp, %1; cvt.u32.u64 %0, tmp; }"
        : "=r"(addr) : "l"(smem_ptr));
    return addr;
}
__device__ __forceinline__ void ldsm_x4(uint32_t* r, uint32_t addr) {
    asm volatile("ldmatrix.sync.aligned.m8n8.x4.shared.b16 {%0,%1,%2,%3}, [%4];"
        : "=r"(r[0]), "=r"(r[1]), "=r"(r[2]), "=r"(r[3]) : "r"(addr));
}
__device__ __forceinline__ void ldsm_x2(uint32_t* r, uint32_t addr) {
    asm volatile("ldmatrix.sync.aligned.m8n8.x2.shared.b16 {%0,%1}, [%2];"
        : "=r"(r[0]), "=r"(r[1]) : "r"(addr));
}
__device__ __forceinline__ void mma_16816(float* c, const uint32_t* a, const uint32_t* b) {
    asm volatile("mma.sync.aligned.m16n8k16.row.col.f32.bf16.bf16.f32 "
        "{%0,%1,%2,%3}, {%4,%5,%6,%7}, {%8,%9}, {%0,%1,%2,%3};"
        : "+f"(c[0]), "+f"(c[1]), "+f"(c[2]), "+f"(c[3])
        : "r"(a[0]), "r"(a[1]), "r"(a[2]), "r"(a[3]), "r"(b[0]), "r"(b[1]));
}
#define CP_ASYNC16(dst, src) \
    asm volatile("cp.async.cg.shared.global [%0], [%1], 16;" :: "r"(dst), "l"(src))
#define CP_COMMIT() asm volatile("cp.async.commit_group;" ::: "memory")
#define CP_WAIT(n)  asm volatile("cp.async.wait_group %0;" :: "n"(n) : "memory")

// ---------- 256-thread compute stage: A rows [0,256), B at 256+d*BD. NF frags/warp ----
template <int NF, int BD>
__device__ __forceinline__ void mma_compute_stage(uint32_t sb, int warp_m, int warp_n,
                                                  int lane, float (*acc)[4])
{
    const int a_row = lane & 15, a_kh = lane >> 4;
#pragma unroll
    for (int ks = 0; ks < 2; ks++) {
        uint32_t af[2][2][4];
#pragma unroll
        for (int d = 0; d < 2; d++)
#pragma unroll
            for (int mi = 0; mi < 2; mi++) {
                int r = d * 128 + warp_m * 32 + mi * 16 + a_row;
                int c = ks * 16 + a_kh * 8;
                ldsm_x4(af[d][mi], sb + (uint32_t)((r * 40 + c) * 2));
            }
        uint32_t bq[2][(NF + 1) / 2][4];
#pragma unroll
        for (int d = 0; d < 2; d++) {
#pragma unroll
            for (int np = 0; np < NF / 2; np++) {
                int r = 256 + d * BD + warp_n * (NF * 8) + np * 16 + (lane & 15);
                int c = ks * 16 + (lane >> 4) * 8;
                ldsm_x4(bq[d][np], sb + (uint32_t)((r * 40 + c) * 2));
            }
            if (NF & 1) {
                int r = 256 + d * BD + warp_n * (NF * 8) + (NF - 1) * 8 + (lane & 7);
                int c = ks * 16 + ((lane >> 3) & 1) * 8;
                ldsm_x2(bq[d][NF / 2], sb + (uint32_t)((r * 40 + c) * 2));
            }
        }
#pragma unroll
        for (int mi = 0; mi < 2; mi++)
#pragma unroll
            for (int ni = 0; ni < NF; ni++) {
                uint32_t fh[2], fl[2];
                if ((NF & 1) && ni == NF - 1) {
                    fh[0] = bq[0][NF / 2][0]; fh[1] = bq[0][NF / 2][1];
                    fl[0] = bq[1][NF / 2][0]; fl[1] = bq[1][NF / 2][1];
                } else {
                    fh[0] = bq[0][ni >> 1][ni & 1]; fh[1] = bq[0][ni >> 1][(ni & 1) + 2];
                    fl[0] = bq[1][ni >> 1][ni & 1]; fl[1] = bq[1][ni >> 1][(ni & 1) + 2];
                }
                mma_16816(acc[mi * NF + ni], af[0][mi], fh);
                mma_16816(acc[mi * NF + ni], af[0][mi], fl);
                mma_16816(acc[mi * NF + ni], af[1][mi], fh);
            }
    }
}

// ====================== static scratch ======================
__device__ float z_buf  [64 * 512 * 784];
__device__ float g_stats[1024];
__device__ float Mpart  [7 * 8 * 256 * 256];
__device__ float Zs1    [896 * 512];
__device__ float Zs2    [896 * 512];

__device__ __nv_bfloat16 wcat_hi[768 * 512], wcat_lo[768 * 512];
__device__ __nv_bfloat16 wW_hi [512 * 256],  wW_lo [512 * 256];
__device__ __nv_bfloat16 xt_hi [64 * 784 * 512], xt_lo[64 * 784 * 512];
__device__ __nv_bfloat16 thetat_hi[8 * 6272 * 256], thetat_lo[8 * 6272 * 256];
__device__ __nv_bfloat16 yt_hi [64 * 784 * 256], yt_lo[64 * 784 * 256];
__device__ __nv_bfloat16 gp_hi [8 * 256 * 1568], gp_lo[8 * 256 * 1568];   // p = sp*8+u
__device__ __nv_bfloat16 pp_hi [8 * 256 * 1568], pp_lo[8 * 256 * 1568];
__device__ __nv_bfloat16 Mt_hi [8 * 256 * 256],  Mt_lo[8 * 256 * 256];

__device__ __forceinline__ void split_store(float v, __nv_bfloat16* hi, __nv_bfloat16* lo,
                                            size_t idx) {
    __nv_bfloat16 h = __float2bfloat16(v);
    hi[idx] = h;
    lo[idx] = __float2bfloat16(v - __bfloat162float(h));
}

// ====================== split/convert kernels ======================
__global__ __launch_bounds__(256) void split_w_kernel(
    const float* __restrict__ wth, const float* __restrict__ wg,
    const float* __restrict__ wph, const float* __restrict__ wW)
{
    int i = blockIdx.x * 256 + threadIdx.x;
    if (i < 393216) {
        int r = i >> 9, k = i & 511;
        const float* w = (r < 256) ? wth : (r < 512) ? wg : wph;
        split_store(w[(r & 255) * 512 + k], wcat_hi, wcat_lo, i);
    } else {
        int j = i - 393216;
        split_store(wW[j], wW_hi, wW_lo, j);
    }
}

__global__ __launch_bounds__(256) void split_x_kernel(const float* __restrict__ x)
{
    __shared__ float t[16][17];
    int img = blockIdx.z;
    int c0 = blockIdx.y * 16, s0 = blockIdx.x * 16;
    const float* src = x + ((size_t)img * 512 + c0) * 784 + s0;
    t[threadIdx.y][threadIdx.x] = src[threadIdx.y * 784 + threadIdx.x];
    __syncthreads();
    float v = t[threadIdx.x][threadIdx.y];
    size_t dst = ((size_t)img * 784 + s0 + threadIdx.y) * 512 + c0 + threadIdx.x;
    split_store(v, xt_hi, xt_lo, dst);
}

__global__ void init_stats()
{
    if (blockIdx.x == 0 && threadIdx.x < 1024) g_stats[threadIdx.x] = 0.f;
}

// ====================== conv GEMM config: 256 thr, 3 stages, 2 CTAs/SM ======
static constexpr int TC_STAGES = 3;
static constexpr int TC_STAGE_BYTES = 480 * 40 * 2;           // 38400
static constexpr int TC_SMEM = TC_STAGES * TC_STAGE_BYTES;    // 115200

// per-thread loader precompute for the 480-row conv layout (items i = tid + j*256)
template <int KDIM>
__device__ __forceinline__ void conv_loader_init(
    int tid,
    const __nv_bfloat16* A_hi, const __nv_bfloat16* A_lo,
    const __nv_bfloat16* B_hi, const __nv_bfloat16* B_lo,
    const __nv_bfloat16* (&srcs)[8], uint32_t& doff0)
{
    doff0 = (uint32_t)(((tid >> 2) * 40 + (tid & 3) * 8) * 2);
#pragma unroll
    for (int j = 0; j < 8; j++) {
        int i = tid + j * 256;
        const __nv_bfloat16* s;
        int kc = i & 3;
        if (i < 1024) {
            int d = i >> 9, r = (i & 511) >> 2;
            s = (d ? A_lo : A_hi) + (size_t)r * KDIM + kc * 8;
        } else {
            int q = i - 1024;
            int d = (q >= 448); if (d) q -= 448;
            int r = q >> 2;
            s = (d ? B_lo : B_hi) + (size_t)r * KDIM + kc * 8;
        }
        srcs[j] = s;
    }
}

__device__ __forceinline__ void conv_load_stage(
    uint32_t sb, uint32_t doff0, const __nv_bfloat16* (&srcs)[8], int k0, int tid)
{
#pragma unroll
    for (int j = 0; j < 7; j++)
        CP_ASYNC16(sb + doff0 + (uint32_t)(j * 5120), srcs[j] + k0);
    if (tid < 128)
        CP_ASYNC16(sb + doff0 + (uint32_t)(7 * 5120), srcs[7] + k0);
}

// ====================== projection GEMM (theta|g|phi) ======================
__global__ __launch_bounds__(256, 2) void proj_gemm_mma(
    const float* __restrict__ bth, const float* __restrict__ bg,
    const float* __restrict__ bph)
{
    constexpr int KDIM = 512;
    constexpr int KITERS = 16;
    extern __shared__ __align__(128) __nv_bfloat16 smem[];
    const uint32_t smem_base = smem_to_u32(smem);

    const int tid = threadIdx.x;
    const int lane = tid & 31;
    const int wid = tid >> 5;
    const int warp_m = wid & 3;
    const int warp_n = wid >> 2;
    const int img = blockIdx.z;
    const int m0 = blockIdx.y * 128;
    const int n0 = blockIdx.x * 112;

    const __nv_bfloat16* srcs[8];
    uint32_t doff0;
    conv_loader_init<KDIM>(tid,
        wcat_hi + (size_t)m0 * KDIM, wcat_lo + (size_t)m0 * KDIM,
        xt_hi + ((size_t)img * 784 + n0) * KDIM, xt_lo + ((size_t)img * 784 + n0) * KDIM,
        srcs, doff0);

    float acc[14][4];
#pragma unroll
    for (int q = 0; q < 14; q++)
#pragma unroll
        for (int r = 0; r < 4; r++) acc[q][r] = 0.f;

#pragma unroll
    for (int s = 0; s < TC_STAGES - 1; s++) {
        conv_load_stage(smem_base + (uint32_t)(s * TC_STAGE_BYTES), doff0, srcs, s * 32, tid);
        CP_COMMIT();
    }

    for (int it = 0; it < KITERS; it++) {
        CP_WAIT(TC_STAGES - 2);
        __syncthreads();
        if (it + TC_STAGES - 1 < KITERS)
            conv_load_stage(smem_base + (uint32_t)(((it + TC_STAGES - 1) % TC_STAGES) * TC_STAGE_BYTES),
                            doff0, srcs, (it + TC_STAGES - 1) * 32, tid);
        CP_COMMIT();
        const uint32_t sb = smem_base + (uint32_t)((it % TC_STAGES) * TC_STAGE_BYTES);
        mma_compute_stage<7, 112>(sb, warp_m, warp_n, lane, acc);
    }
    __syncthreads();

    // ---- stage C + bias into SMEM fp32 [128 ch][pitch 113 spatial] ----
    const int region = m0 >> 8;             // 0 theta, 1 g, 2 phi
    const int mloc = m0 & 255;
    const float* bias = (region == 0) ? bth : (region == 1) ? bg : bph;
    float* smf = reinterpret_cast<float*>(smem);

#pragma unroll
    for (int mi = 0; mi < 2; mi++) {
        int r0 = warp_m * 32 + mi * 16 + (lane >> 2);
        float bv0 = bias[mloc + r0];
        float bv1 = bias[mloc + r0 + 8];
#pragma unroll
        for (int ni = 0; ni < 7; ni++) {
            int col = warp_n * 56 + ni * 8 + (lane & 3) * 2;
            smf[r0 * 113 + col]           = acc[mi * 7 + ni][0] + bv0;
            smf[r0 * 113 + col + 1]       = acc[mi * 7 + ni][1] + bv0;
            smf[(r0 + 8) * 113 + col]     = acc[mi * 7 + ni][2] + bv1;
            smf[(r0 + 8) * 113 + col + 1] = acc[mi * 7 + ni][3] + bv1;
        }
    }
    __syncthreads();

    const int b = img >> 3, r = img & 7;
    const int cibase = r * 32 + (mloc >> 3);   // multiple of 16

    if (region == 0) {
        for (int item = tid; item < 896; item += 256) {
            int sl = item >> 3, u = item & 7;
            int t = u * 784 + n0 + sl;
            size_t dstb = ((size_t)b * 6272 + t) * 256 + cibase;
            __nv_bfloat16 hv[16], lv[16];
#pragma unroll
            for (int q = 0; q < 16; q++) {
                float v = smf[(q * 8 + u) * 113 + sl];
                __nv_bfloat16 h = __float2bfloat16(v);
                hv[q] = h;
                lv[q] = __float2bfloat16(v - __bfloat162float(h));
            }
            *reinterpret_cast<uint4*>(thetat_hi + dstb)     = reinterpret_cast<uint4*>(hv)[0];
            *reinterpret_cast<uint4*>(thetat_hi + dstb + 8) = reinterpret_cast<uint4*>(hv)[1];
            *reinterpret_cast<uint4*>(thetat_lo + dstb)     = reinterpret_cast<uint4*>(lv)[0];
            *reinterpret_cast<uint4*>(thetat_lo + dstb + 8) = reinterpret_cast<uint4*>(lv)[1];
        }
    } else {
        __nv_bfloat16* hi = (region == 1) ? gp_hi : pp_hi;
        __nv_bfloat16* lo = (region == 1) ? gp_lo : pp_lo;
        {
            int cc = tid & 127, pr = tid >> 7;
            int ci = cibase + (cc >> 3);
            int u = cc & 7;
            size_t base = ((size_t)b * 256 + ci) * 1568 + (size_t)u;
            int spbase = (2 * blockIdx.x + pr) * 14;
#pragma unroll
            for (int pc = 0; pc < 14; pc++) {
                const float* p = &smf[cc * 113 + pr * 56 + pc * 2];
                float v = fmaxf(fmaxf(p[0], p[1]), fmaxf(p[28], p[29]));
                split_store(v, hi, lo, base + (size_t)(spbase + pc) * 8);
            }
        }
    }
}

// ====================== z GEMM + fused BN partial stats ======================
__global__ __launch_bounds__(256, 2) void mma_z_gemm(const float* __restrict__ biasb)
{
    constexpr int KDIM = 256;
    constexpr int KITERS = 8;
    extern __shared__ __align__(128) __nv_bfloat16 smem[];
    const uint32_t smem_base = smem_to_u32(smem);

    const int tid = threadIdx.x;
    const int lane = tid & 31;
    const int wid = tid >> 5;
    const int warp_m = wid & 3;
    const int warp_n = wid >> 2;
    const int img = blockIdx.z;
    const int m0 = blockIdx.y * 128;
    const int n0 = blockIdx.x * 112;

    const __nv_bfloat16* srcs[8];
    uint32_t doff0;
    conv_loader_init<KDIM>(tid,
        wW_hi + (size_t)m0 * KDIM, wW_lo + (size_t)m0 * KDIM,
        yt_hi + ((size_t)img * 784 + n0) * KDIM, yt_lo + ((size_t)img * 784 + n0) * KDIM,
        srcs, doff0);

    float acc[14][4];
#pragma unroll
    for (int q = 0; q < 14; q++)
#pragma unroll
        for (int r = 0; r < 4; r++) acc[q][r] = 0.f;

#pragma unroll
    for (int s = 0; s < TC_STAGES - 1; s++) {
        conv_load_stage(smem_base + (uint32_t)(s * TC_STAGE_BYTES), doff0, srcs, s * 32, tid);
        CP_COMMIT();
    }

    for (int it = 0; it < KITERS; it++) {
        CP_WAIT(TC_STAGES - 2);
        __syncthreads();
        if (it + TC_STAGES - 1 < KITERS)
            conv_load_stage(smem_base + (uint32_t)(((it + TC_STAGES - 1) % TC_STAGES) * TC_STAGE_BYTES),
                            doff0, srcs, (it + TC_STAGES - 1) * 32, tid);
        CP_COMMIT();
        const uint32_t sb = smem_base + (uint32_t)((it % TC_STAGES) * TC_STAGE_BYTES);
        mma_compute_stage<7, 112>(sb, warp_m, warp_n, lane, acc);
    }

    float* outp = z_buf + (size_t)img * 512 * 784 + (size_t)m0 * 784;
    const int part = (img * 7 + blockIdx.x) * 2 + warp_n;
#pragma unroll
    for (int mi = 0; mi < 2; mi++) {
        int r0 = warp_m * 32 + mi * 16 + (lane >> 2);
        float bv0 = biasb[m0 + r0];
        float bv1 = biasb[m0 + r0 + 8];
        float s1a = 0.f, s2a = 0.f, s1b = 0.f, s2b = 0.f;
#pragma unroll
        for (int ni = 0; ni < 7; ni++) {
            int col = n0 + warp_n * 56 + ni * 8 + (lane & 3) * 2;
            float a0 = acc[mi * 7 + ni][0] + bv0;
            float a1 = acc[mi * 7 + ni][1] + bv0;
            float a2 = acc[mi * 7 + ni][2] + bv1;
            float a3 = acc[mi * 7 + ni][3] + bv1;
            s1a += a0 + a1; s2a += a0 * a0 + a1 * a1;
            s1b += a2 + a3; s2b += a2 * a2 + a3 * a3;
            *reinterpret_cast<float2*>(outp + (size_t)r0 * 784 + col) = make_float2(a0, a1);
            *reinterpret_cast<float2*>(outp + (size_t)(r0 + 8) * 784 + col) = make_float2(a2, a3);
        }
        s1a += __shfl_xor_sync(0xffffffff, s1a, 1); s1a += __shfl_xor_sync(0xffffffff, s1a, 2);
        s2a += __shfl_xor_sync(0xffffffff, s2a, 1); s2a += __shfl_xor_sync(0xffffffff, s2a, 2);
        s1b += __shfl_xor_sync(0xffffffff, s1b, 1); s1b += __shfl_xor_sync(0xffffffff, s1b, 2);
        s2b += __shfl_xor_sync(0xffffffff, s2b, 1); s2b += __shfl_xor_sync(0xffffffff, s2b, 2);
        if ((lane & 3) == 0) {
            Zs1[(size_t)part * 512 + m0 + r0]     = s1a;
            Zs2[(size_t)part * 512 + m0 + r0]     = s2a;
            Zs1[(size_t)part * 512 + m0 + r0 + 8] = s1b;
            Zs2[(size_t)part * 512 + m0 + r0 + 8] = s2b;
        }
    }
}

// ---- reduce BN partials ----
__global__ __launch_bounds__(256) void reduce_stats()
{
    const int c = blockIdx.x;
    float s1 = 0.f, s2 = 0.f;
    for (int p = threadIdx.x; p < 896; p += 256) {
        s1 += Zs1[(size_t)p * 512 + c];
        s2 += Zs2[(size_t)p * 512 + c];
    }
    __shared__ float r1[256], r2[256];
    r1[threadIdx.x] = s1; r2[threadIdx.x] = s2;
    __syncthreads();
    for (int off = 128; off > 0; off >>= 1) {
        if (threadIdx.x < off) {
            r1[threadIdx.x] += r1[threadIdx.x + off];
            r2[threadIdx.x] += r2[threadIdx.x + off];
        }
        __syncthreads();
    }
    if (threadIdx.x == 0) { g_stats[c] = r1[0]; g_stats[512 + c] = r2[0]; }
}

// ====================== attention GEMM config: N-tile 64, 2 CTAs/SM ======
static constexpr int SQ_STAGES = 3;
static constexpr int SQ_STAGE_BYTES = 384 * 40 * 2;             // 30720
static constexpr int SQ_SMEM = SQ_STAGES * SQ_STAGE_BYTES;      // 92160

// ---- split-K nt_M: tile 128(i) x 64(j) ----
__global__ __launch_bounds__(256, 2) void mma_nt_M_split()
{
    extern __shared__ __align__(128) __nv_bfloat16 smem[];
    const uint32_t smem_base = smem_to_u32(smem);
    const int tid = threadIdx.x, lane = tid & 31, wid = tid >> 5;
    const int warp_m = wid & 3, warp_n = wid >> 2;
    const int b = blockIdx.z;
    const int sl = blockIdx.y;
    const int i0 = (blockIdx.x >> 2) * 128;
    const int j0 = (blockIdx.x & 3) * 64;
    const int kbase = sl * 224;

    const __nv_bfloat16* A_hi = pp_hi + ((size_t)b * 256 + i0) * 1568 + kbase;
    const __nv_bfloat16* A_lo = pp_lo + ((size_t)b * 256 + i0) * 1568 + kbase;
    const __nv_bfloat16* B_hi = gp_hi + ((size_t)b * 256 + j0) * 1568 + kbase;
    const __nv_bfloat16* B_lo = gp_lo + ((size_t)b * 256 + j0) * 1568 + kbase;

    // precompute 6 per-thread source pointers (items i = tid + j*256, rows = i>>2)
    const __nv_bfloat16* srcs[6];
    const uint32_t doff0 = (uint32_t)(((tid >> 2) * 40 + (tid & 3) * 8) * 2);
#pragma unroll
    for (int j = 0; j < 6; j++) {
        int i = tid + j * 256;
        int row = i >> 2, kc = i & 3;
        const __nv_bfloat16* s;
        if (row < 128)      s = A_hi + (size_t)row * 1568 + kc * 8;
        else if (row < 256) s = A_lo + (size_t)(row - 128) * 1568 + kc * 8;
        else if (row < 320) s = B_hi + (size_t)(row - 256) * 1568 + kc * 8;
        else                s = B_lo + (size_t)(row - 320) * 1568 + kc * 8;
        srcs[j] = s;
    }
    auto load_stage = [&](uint32_t sb, int k0) {
#pragma unroll
        for (int j = 0; j < 6; j++)
            CP_ASYNC16(sb + doff0 + (uint32_t)(j * 5120), srcs[j] + k0);
    };

    float acc[8][4];
#pragma unroll
    for (int q = 0; q < 8; q++)
#pragma unroll
        for (int r = 0; r < 4; r++) acc[q][r] = 0.f;

#pragma unroll
    for (int s = 0; s < SQ_STAGES - 1; s++) {
        load_stage(smem_base + (uint32_t)(s * SQ_STAGE_BYTES), s * 32);
        CP_COMMIT();
    }

    for (int it = 0; it < 7; it++) {
        CP_WAIT(SQ_STAGES - 2);
        __syncthreads();
        if (it + SQ_STAGES - 1 < 7)
            load_stage(smem_base + (uint32_t)(((it + SQ_STAGES - 1) % SQ_STAGES) * SQ_STAGE_BYTES),
                       (it + SQ_STAGES - 1) * 32);
        CP_COMMIT();
        const uint32_t sb = smem_base + (uint32_t)((it % SQ_STAGES) * SQ_STAGE_BYTES);
        mma_compute_stage<4, 64>(sb, warp_m, warp_n, lane, acc);
    }

    float* outp = Mpart + ((size_t)(sl * 8 + b)) * 65536;
#pragma unroll
    for (int mi = 0; mi < 2; mi++) {
        int ri = i0 + warp_m * 32 + mi * 16 + (lane >> 2);
#pragma unroll
        for (int ni = 0; ni < 4; ni++) {
            int col = j0 + warp_n * 32 + ni * 8 + (lane & 3) * 2;
            *reinterpret_cast<float2*>(outp + (size_t)ri * 256 + col) =
                make_float2(acc[mi * 4 + ni][0], acc[mi * 4 + ni][1]);
            *reinterpret_cast<float2*>(outp + (size_t)(ri + 8) * 256 + col) =
                make_float2(acc[mi * 4 + ni][2], acc[mi * 4 + ni][3]);
        }
    }
}

// ---- reduce 7 partials, scale, transpose -> Mt bf16 split ----
__global__ __launch_bounds__(256) void reduce_M()
{
    int idx = blockIdx.x * 256 + threadIdx.x;
    int b = idx >> 16, j = (idx >> 8) & 255, i = idx & 255;
    float s = 0.f;
#pragma unroll
    for (int sl = 0; sl < 7; sl++)
        s += Mpart[((size_t)(sl * 8 + b)) * 65536 + (size_t)i * 256 + j];
    split_store(s * (1.0f / 1568.0f), Mt_hi, Mt_lo, (size_t)idx);
}

// ---- tn_y: tile 128(t) x 64(cg), gathered M-tile, coalesced yt stores ----
__global__ __launch_bounds__(256, 2) void mma_tn_y()
{
    extern __shared__ __align__(128) __nv_bfloat16 smem[];
    const uint32_t smem_base = smem_to_u32(smem);
    const int tid = threadIdx.x, lane = tid & 31, wid = tid >> 5;
    const int warp_m = wid & 3, warp_n = wid >> 2;
    const int b = blockIdx.z;
    const int s0 = blockIdx.y * 16;
    const int n0 = blockIdx.x * 64;

    const __nv_bfloat16* srcs[6];
    const uint32_t doff0 = (uint32_t)(((tid >> 2) * 40 + (tid & 3) * 8) * 2);
#pragma unroll
    for (int j = 0; j < 6; j++) {
        int i = tid + j * 256;
        int row = i >> 2, kc = i & 3;
        const __nv_bfloat16* s;
        if (row < 256) {
            int d = row >> 7, rl = row & 127;
            int t = (rl >> 4) * 784 + s0 + (rl & 15);
            s = (d ? thetat_lo : thetat_hi) + ((size_t)b * 6272 + t) * 256 + kc * 8;
        } else if (row < 320) {
            s = Mt_hi + ((size_t)b * 256 + n0 + (row - 256)) * 256 + kc * 8;
        } else {
            s = Mt_lo + ((size_t)b * 256 + n0 + (row - 320)) * 256 + kc * 8;
        }
        srcs[j] = s;
    }
    auto load_stage = [&](uint32_t sb, int k0) {
#pragma unroll
        for (int j = 0; j < 6; j++)
            CP_ASYNC16(sb + doff0 + (uint32_t)(j * 5120), srcs[j] + k0);
    };

    float acc[8][4];
#pragma unroll
    for (int q = 0; q < 8; q++)
#pragma unroll
        for (int r = 0; r < 4; r++) acc[q][r] = 0.f;

#pragma unroll
    for (int s = 0; s < SQ_STAGES - 1; s++) {
        load_stage(smem_base + (uint32_t)(s * SQ_STAGE_BYTES), s * 32);
        CP_COMMIT();
    }

    for (int it = 0; it < 8; it++) {
        CP_WAIT(SQ_STAGES - 2);
        __syncthreads();
        if (it + SQ_STAGES - 1 < 8)
            load_stage(smem_base + (uint32_t)(((it + SQ_STAGES - 1) % SQ_STAGES) * SQ_STAGE_BYTES),
                       (it + SQ_STAGES - 1) * 32);
        CP_COMMIT();
        const uint32_t sb = smem_base + (uint32_t)((it % SQ_STAGES) * SQ_STAGE_BYTES);
        mma_compute_stage<4, 64>(sb, warp_m, warp_n, lane, acc);
    }
    __syncthreads();

    float* smf = reinterpret_cast<float*>(smem);
#pragma unroll
    for (int mi = 0; mi < 2; mi++) {
        int r0 = warp_m * 32 + mi * 16 + (lane >> 2);
#pragma unroll
        for (int ni = 0; ni < 4; ni++) {
            int col = warp_n * 32 + ni * 8 + (lane & 3) * 2;
            smf[r0 * 65 + col]           = acc[mi * 4 + ni][0];
            smf[r0 * 65 + col + 1]       = acc[mi * 4 + ni][1];
            smf[(r0 + 8) * 65 + col]     = acc[mi * 4 + ni][2];
            smf[(r0 + 8) * 65 + col + 1] = acc[mi * 4 + ni][3];
        }
    }
    __syncthreads();

    for (int v = tid; v < 1024; v += 256) {
        int kk = v & 31;
        int si = (v >> 5) & 15;
        int ig = v >> 9;
        int col = ig * 32 + kk;
        int cg = n0 + col;
        int img = 8 * b + (cg >> 5);
        int c0 = (cg & 31) * 8;
        __nv_bfloat16 hv[8], lv[8];
#pragma unroll
        for (int tq = 0; tq < 8; tq++) {
            float xv = smf[(tq * 16 + si) * 65 + col];
            __nv_bfloat16 h = __float2bfloat16(xv);
            hv[tq] = h;
            lv[tq] = __float2bfloat16(xv - __bfloat162float(h));
        }
        size_t dst = ((size_t)img * 784 + s0 + si) * 256 + c0;
        *reinterpret_cast<uint4*>(yt_hi + dst) = *reinterpret_cast<uint4*>(hv);
        *reinterpret_cast<uint4*>(yt_lo + dst) = *reinterpret_cast<uint4*>(lv);
    }
}

// ====================== BN apply + residual ======================
__global__ __launch_bounds__(256) void bn_res(
    const float* __restrict__ x,
    const float* __restrict__ gamma, const float* __restrict__ beta,
    float* __restrict__ out)
{
    const int i4 = blockIdx.x * 256 + threadIdx.x;
    const int c = (i4 / 196) & 511;
    const float inv_cnt = 1.0f / 50176.0f;
    float mean = g_stats[c] * inv_cnt;
    float var  = g_stats[512 + c] * inv_cnt - mean * mean;
    float sc = gamma[c] * rsqrtf(var + 1e-5f);
    float sh = beta[c] - mean * sc;
    float4 zv = reinterpret_cast<const float4*>(z_buf)[i4];
    float4 xv = reinterpret_cast<const float4*>(x)[i4];
    float4 o;
    o.x = zv.x * sc + sh + xv.x;
    o.y = zv.y * sc + sh + xv.y;
    o.z = zv.z * sc + sh + xv.z;
    o.w = zv.w * sc + sh + xv.w;
    reinterpret_cast<float4*>(out)[i4] = o;
}

// ====================== launcher ======================
extern "C" void kernel_launch(void* const* d_in, const int* in_sizes, int n_in,
                              void* d_out, int out_size)
{
    const float* x     = (const float*)d_in[0];
    const float* wg    = (const float*)d_in[1];
    const float* bg    = (const float*)d_in[2];
    const float* wth   = (const float*)d_in[3];
    const float* bth   = (const float*)d_in[4];
    const float* wph   = (const float*)d_in[5];
    const float* bph   = (const float*)d_in[6];
    const float* wW    = (const float*)d_in[7];
    const float* bW    = (const float*)d_in[8];
    const float* gamma = (const float*)d_in[9];
    const float* beta  = (const float*)d_in[10];
    float* out = (float*)d_out;

    cudaFuncSetAttribute(proj_gemm_mma,
                         cudaFuncAttributeMaxDynamicSharedMemorySize, TC_SMEM);
    cudaFuncSetAttribute(mma_z_gemm,
                         cudaFuncAttributeMaxDynamicSharedMemorySize, TC_SMEM);
    cudaFuncSetAttribute(mma_nt_M_split,
                         cudaFuncAttributeMaxDynamicSharedMemorySize, SQ_SMEM);
    cudaFuncSetAttribute(mma_tn_y,
                         cudaFuncAttributeMaxDynamicSharedMemorySize, SQ_SMEM);

    split_w_kernel<<<2048, 256>>>(wth, wg, wph, wW);
    split_x_kernel<<<dim3(49, 32, 64), dim3(16, 16)>>>(x);
    init_stats<<<1, 1024>>>();                       // proj at profiled slot

    proj_gemm_mma<<<dim3(7, 6, 64), 256, TC_SMEM>>>(bth, bg, bph);

    mma_nt_M_split<<<dim3(8, 7, 8), 256, SQ_SMEM>>>();
    reduce_M<<<2048, 256>>>();
    mma_tn_y<<<dim3(4, 49, 8), 256, SQ_SMEM>>>();

    mma_z_gemm<<<dim3(7, 4, 64), 256, TC_SMEM>>>(bW);
    reduce_stats<<<512, 256>>>();

    bn_res<<<25088, 256>>>(x, gamma, beta, out);
}

// round 15
// speedup vs baseline: 1.0318x; 1.0318x over previous
#include <cuda_runtime.h>
#include <cuda_bf16.h>
#include <cstdint>

// ====================== mma.sync helpers ======================
__device__ __forceinline__ uint32_t smem_to_u32(const void* smem_ptr) {
    uint32_t addr;
    asm("{ .reg .u64 tmp; cvta.to.shared.u64 tmp, %1; cvt.u32.u64 %0, tmp; }"
        : "=r"(addr) : "l"(smem_ptr));
    return addr;
}
__device__ __forceinline__ void ldsm_x4(uint32_t* r, uint32_t addr) {
    asm volatile("ldmatrix.sync.aligned.m8n8.x4.shared.b16 {%0,%1,%2,%3}, [%4];"
        : "=r"(r[0]), "=r"(r[1]), "=r"(r[2]), "=r"(r[3]) : "r"(addr));
}
__device__ __forceinline__ void ldsm_x2(uint32_t* r, uint32_t addr) {
    asm volatile("ldmatrix.sync.aligned.m8n8.x2.shared.b16 {%0,%1}, [%2];"
        : "=r"(r[0]), "=r"(r[1]) : "r"(addr));
}
__device__ __forceinline__ void mma_16816(float* c, const uint32_t* a, const uint32_t* b) {
    asm volatile("mma.sync.aligned.m16n8k16.row.col.f32.bf16.bf16.f32 "
        "{%0,%1,%2,%3}, {%4,%5,%6,%7}, {%8,%9}, {%0,%1,%2,%3};"
        : "+f"(c[0]), "+f"(c[1]), "+f"(c[2]), "+f"(c[3])
        : "r"(a[0]), "r"(a[1]), "r"(a[2]), "r"(a[3]), "r"(b[0]), "r"(b[1]));
}
#define CP_ASYNC16(dst, src) \
    asm volatile("cp.async.cg.shared.global [%0], [%1], 16;" :: "r"(dst), "l"(src))
#define CP_COMMIT() asm volatile("cp.async.commit_group;" ::: "memory")
#define CP_WAIT(n)  asm volatile("cp.async.wait_group %0;" :: "n"(n) : "memory")

// ---------- 256-thread compute stage: A rows [0,256), B at 256+d*BD. NF frags/warp ----
template <int NF, int BD>
__device__ __forceinline__ void mma_compute_stage(uint32_t sb, int warp_m, int warp_n,
                                                  int lane, float (*acc)[4])
{
    const int a_row = lane & 15, a_kh = lane >> 4;
#pragma unroll
    for (int ks = 0; ks < 2; ks++) {
        uint32_t af[2][2][4];
#pragma unroll
        for (int d = 0; d < 2; d++)
#pragma unroll
            for (int mi = 0; mi < 2; mi++) {
                int r = d * 128 + warp_m * 32 + mi * 16 + a_row;
                int c = ks * 16 + a_kh * 8;
                ldsm_x4(af[d][mi], sb + (uint32_t)((r * 40 + c) * 2));
            }
        uint32_t bq[2][(NF + 1) / 2][4];
#pragma unroll
        for (int d = 0; d < 2; d++) {
#pragma unroll
            for (int np = 0; np < NF / 2; np++) {
                int r = 256 + d * BD + warp_n * (NF * 8) + np * 16 + (lane & 15);
                int c = ks * 16 + (lane >> 4) * 8;
                ldsm_x4(bq[d][np], sb + (uint32_t)((r * 40 + c) * 2));
            }
            if (NF & 1) {
                int r = 256 + d * BD + warp_n * (NF * 8) + (NF - 1) * 8 + (lane & 7);
                int c = ks * 16 + ((lane >> 3) & 1) * 8;
                ldsm_x2(bq[d][NF / 2], sb + (uint32_t)((r * 40 + c) * 2));
            }
        }
#pragma unroll
        for (int mi = 0; mi < 2; mi++)
#pragma unroll
            for (int ni = 0; ni < NF; ni++) {
                uint32_t fh[2], fl[2];
                if ((NF & 1) && ni == NF - 1) {
                    fh[0] = bq[0][NF / 2][0]; fh[1] = bq[0][NF / 2][1];
                    fl[0] = bq[1][NF / 2][0]; fl[1] = bq[1][NF / 2][1];
                } else {
                    fh[0] = bq[0][ni >> 1][ni & 1]; fh[1] = bq[0][ni >> 1][(ni & 1) + 2];
                    fl[0] = bq[1][ni >> 1][ni & 1]; fl[1] = bq[1][ni >> 1][(ni & 1) + 2];
                }
                mma_16816(acc[mi * NF + ni], af[0][mi], fh);
                mma_16816(acc[mi * NF + ni], af[0][mi], fl);
                mma_16816(acc[mi * NF + ni], af[1][mi], fh);
            }
    }
}

// ====================== static scratch ======================
__device__ float z_buf  [64 * 512 * 784];
__device__ float g_stats[1024];
__device__ float Mpart  [7 * 8 * 256 * 256];
__device__ float Zs1    [896 * 512];
__device__ float Zs2    [896 * 512];

__device__ __nv_bfloat16 wcat_hi[768 * 512], wcat_lo[768 * 512];
__device__ __nv_bfloat16 wW_hi [512 * 256],  wW_lo [512 * 256];
__device__ __nv_bfloat16 xt_hi [64 * 784 * 512], xt_lo[64 * 784 * 512];
__device__ __nv_bfloat16 thetat_hi[8 * 6272 * 256], thetat_lo[8 * 6272 * 256];
__device__ __nv_bfloat16 yt_hi [64 * 784 * 256], yt_lo[64 * 784 * 256];
__device__ __nv_bfloat16 gp_hi [8 * 256 * 1568], gp_lo[8 * 256 * 1568];   // p = sp*8+u
__device__ __nv_bfloat16 pp_hi [8 * 256 * 1568], pp_lo[8 * 256 * 1568];
__device__ __nv_bfloat16 Mt_hi [8 * 256 * 256],  Mt_lo[8 * 256 * 256];

__device__ __forceinline__ void split_store(float v, __nv_bfloat16* hi, __nv_bfloat16* lo,
                                            size_t idx) {
    __nv_bfloat16 h = __float2bfloat16(v);
    hi[idx] = h;
    lo[idx] = __float2bfloat16(v - __bfloat162float(h));
}

// ====================== split/convert kernels ======================
__global__ __launch_bounds__(256) void split_w_kernel(
    const float* __restrict__ wth, const float* __restrict__ wg,
    const float* __restrict__ wph, const float* __restrict__ wW)
{
    int i = blockIdx.x * 256 + threadIdx.x;
    if (i < 393216) {
        int r = i >> 9, k = i & 511;
        const float* w = (r < 256) ? wth : (r < 512) ? wg : wph;
        split_store(w[(r & 255) * 512 + k], wcat_hi, wcat_lo, i);
    } else {
        int j = i - 393216;
        split_store(wW[j], wW_hi, wW_lo, j);
    }
}

__global__ __launch_bounds__(256) void split_x_kernel(const float* __restrict__ x)
{
    __shared__ float t[16][17];
    int img = blockIdx.z;
    int c0 = blockIdx.y * 16, s0 = blockIdx.x * 16;
    const float* src = x + ((size_t)img * 512 + c0) * 784 + s0;
    t[threadIdx.y][threadIdx.x] = src[threadIdx.y * 784 + threadIdx.x];
    __syncthreads();
    float v = t[threadIdx.x][threadIdx.y];
    size_t dst = ((size_t)img * 784 + s0 + threadIdx.y) * 512 + c0 + threadIdx.x;
    split_store(v, xt_hi, xt_lo, dst);
}

__global__ void init_stats()
{
    if (blockIdx.x == 0 && threadIdx.x < 1024) g_stats[threadIdx.x] = 0.f;
}

// ====================== conv GEMM config: 256 thr, 3 stages, 2 CTAs/SM ======
static constexpr int TC_STAGES = 3;
static constexpr int TC_STAGE_BYTES = 480 * 40 * 2;           // 38400
static constexpr int TC_SMEM = TC_STAGES * TC_STAGE_BYTES;    // 115200

// ====================== projection GEMM (theta|g|phi) ======================
__global__ __launch_bounds__(256, 2) void proj_gemm_mma(
    const float* __restrict__ bth, const float* __restrict__ bg,
    const float* __restrict__ bph)
{
    constexpr int KDIM = 512;
    constexpr int KITERS = 16;
    extern __shared__ __align__(128) __nv_bfloat16 smem[];
    const uint32_t smem_base = smem_to_u32(smem);

    const int tid = threadIdx.x;
    const int lane = tid & 31;
    const int wid = tid >> 5;
    const int warp_m = wid & 3;
    const int warp_n = wid >> 2;
    const int img = blockIdx.z;
    const int m0 = blockIdx.y * 128;
    const int n0 = blockIdx.x * 112;

    const __nv_bfloat16* A_hi = wcat_hi + (size_t)m0 * KDIM;
    const __nv_bfloat16* A_lo = wcat_lo + (size_t)m0 * KDIM;
    const __nv_bfloat16* B_hi = xt_hi + ((size_t)img * 784 + n0) * KDIM;
    const __nv_bfloat16* B_lo = xt_lo + ((size_t)img * 784 + n0) * KDIM;

    auto load_stage = [&](int st, int k0) {
        const uint32_t sb = smem_base + (uint32_t)(st * TC_STAGE_BYTES);
        for (int i = tid; i < 1920; i += 256) {
            int row, kc;
            const __nv_bfloat16* src;
            int dst_row;
            if (i < 1024) {
                int d = i >> 9, j = i & 511;
                row = j >> 2; kc = j & 3;
                src = (d ? A_lo : A_hi) + (size_t)row * KDIM + k0 + kc * 8;
                dst_row = d * 128 + row;
            } else {
                int j = i - 1024;
                int d = (j >= 448); if (d) j -= 448;
                row = j >> 2; kc = j & 3;
                src = (d ? B_lo : B_hi) + (size_t)row * KDIM + k0 + kc * 8;
                dst_row = 256 + d * 112 + row;
            }
            uint32_t dst = sb + (uint32_t)((dst_row * 40 + kc * 8) * 2);
            CP_ASYNC16(dst, src);
        }
    };

    float acc[14][4];
#pragma unroll
    for (int q = 0; q < 14; q++)
#pragma unroll
        for (int r = 0; r < 4; r++) acc[q][r] = 0.f;

#pragma unroll
    for (int s = 0; s < TC_STAGES - 1; s++) { load_stage(s, s * 32); CP_COMMIT(); }

    for (int it = 0; it < KITERS; it++) {
        CP_WAIT(TC_STAGES - 2);
        __syncthreads();
        if (it + TC_STAGES - 1 < KITERS)
            load_stage((it + TC_STAGES - 1) % TC_STAGES, (it + TC_STAGES - 1) * 32);
        CP_COMMIT();
        const uint32_t sb = smem_base + (uint32_t)((it % TC_STAGES) * TC_STAGE_BYTES);
        mma_compute_stage<7, 112>(sb, warp_m, warp_n, lane, acc);
    }
    __syncthreads();

    // ---- stage C + bias into SMEM fp32 [128 ch][pitch 113 spatial] ----
    const int region = m0 >> 8;             // 0 theta, 1 g, 2 phi
    const int mloc = m0 & 255;
    const float* bias = (region == 0) ? bth : (region == 1) ? bg : bph;
    float* smf = reinterpret_cast<float*>(smem);

#pragma unroll
    for (int mi = 0; mi < 2; mi++) {
        int r0 = warp_m * 32 + mi * 16 + (lane >> 2);
        float bv0 = bias[mloc + r0];
        float bv1 = bias[mloc + r0 + 8];
#pragma unroll
        for (int ni = 0; ni < 7; ni++) {
            int col = warp_n * 56 + ni * 8 + (lane & 3) * 2;
            smf[r0 * 113 + col]           = acc[mi * 7 + ni][0] + bv0;
            smf[r0 * 113 + col + 1]       = acc[mi * 7 + ni][1] + bv0;
            smf[(r0 + 8) * 113 + col]     = acc[mi * 7 + ni][2] + bv1;
            smf[(r0 + 8) * 113 + col + 1] = acc[mi * 7 + ni][3] + bv1;
        }
    }
    __syncthreads();

    const int b = img >> 3, r = img & 7;
    const int cibase = r * 32 + (mloc >> 3);   // multiple of 16

    if (region == 0) {
        // theta -> thetat[b][t][ci]: 16 consecutive ci per item, uint4 stores
        for (int item = tid; item < 896; item += 256) {
            int sl = item >> 3, u = item & 7;
            int t = u * 784 + n0 + sl;
            size_t dstb = ((size_t)b * 6272 + t) * 256 + cibase;
            __nv_bfloat16 hv[16], lv[16];
#pragma unroll
            for (int q = 0; q < 16; q++) {
                float v = smf[(q * 8 + u) * 113 + sl];
                __nv_bfloat16 h = __float2bfloat16(v);
                hv[q] = h;
                lv[q] = __float2bfloat16(v - __bfloat162float(h));
            }
            *reinterpret_cast<uint4*>(thetat_hi + dstb)     = reinterpret_cast<uint4*>(hv)[0];
            *reinterpret_cast<uint4*>(thetat_hi + dstb + 8) = reinterpret_cast<uint4*>(hv)[1];
            *reinterpret_cast<uint4*>(thetat_lo + dstb)     = reinterpret_cast<uint4*>(lv)[0];
            *reinterpret_cast<uint4*>(thetat_lo + dstb + 8) = reinterpret_cast<uint4*>(lv)[1];
        }
    } else {
        // g/phi: 2x2 pool -> [b][ci][p], ci = cibase + (cc>>3), p = sp*8 + (cc&7)
        __nv_bfloat16* hi = (region == 1) ? gp_hi : pp_hi;
        __nv_bfloat16* lo = (region == 1) ? gp_lo : pp_lo;
        {
            int cc = tid & 127, pr = tid >> 7;
            int ci = cibase + (cc >> 3);
            int u = cc & 7;
            size_t base = ((size_t)b * 256 + ci) * 1568 + (size_t)u;
            int spbase = (2 * blockIdx.x + pr) * 14;
#pragma unroll
            for (int pc = 0; pc < 14; pc++) {
                const float* p = &smf[cc * 113 + pr * 56 + pc * 2];
                float v = fmaxf(fmaxf(p[0], p[1]), fmaxf(p[28], p[29]));
                split_store(v, hi, lo, base + (size_t)(spbase + pc) * 8);
            }
        }
    }
}

// ====================== z GEMM + fused BN partial stats ======================
__global__ __launch_bounds__(256, 2) void mma_z_gemm(const float* __restrict__ biasb)
{
    constexpr int KDIM = 256;
    constexpr int KITERS = 8;
    extern __shared__ __align__(128) __nv_bfloat16 smem[];
    const uint32_t smem_base = smem_to_u32(smem);

    const int tid = threadIdx.x;
    const int lane = tid & 31;
    const int wid = tid >> 5;
    const int warp_m = wid & 3;
    const int warp_n = wid >> 2;
    const int img = blockIdx.z;
    const int m0 = blockIdx.y * 128;
    const int n0 = blockIdx.x * 112;

    const __nv_bfloat16* A_hi = wW_hi + (size_t)m0 * KDIM;
    const __nv_bfloat16* A_lo = wW_lo + (size_t)m0 * KDIM;
    const __nv_bfloat16* B_hi = yt_hi + ((size_t)img * 784 + n0) * KDIM;
    const __nv_bfloat16* B_lo = yt_lo + ((size_t)img * 784 + n0) * KDIM;

    auto load_stage = [&](int st, int k0) {
        const uint32_t sb = smem_base + (uint32_t)(st * TC_STAGE_BYTES);
        for (int i = tid; i < 1920; i += 256) {
            int row, kc;
            const __nv_bfloat16* src;
            int dst_row;
            if (i < 1024) {
                int d = i >> 9, j = i & 511;
                row = j >> 2; kc = j & 3;
                src = (d ? A_lo : A_hi) + (size_t)row * KDIM + k0 + kc * 8;
                dst_row = d * 128 + row;
            } else {
                int j = i - 1024;
                int d = (j >= 448); if (d) j -= 448;
                row = j >> 2; kc = j & 3;
                src = (d ? B_lo : B_hi) + (size_t)row * KDIM + k0 + kc * 8;
                dst_row = 256 + d * 112 + row;
            }
            uint32_t dst = sb + (uint32_t)((dst_row * 40 + kc * 8) * 2);
            CP_ASYNC16(dst, src);
        }
    };

    float acc[14][4];
#pragma unroll
    for (int q = 0; q < 14; q++)
#pragma unroll
        for (int r = 0; r < 4; r++) acc[q][r] = 0.f;

#pragma unroll
    for (int s = 0; s < TC_STAGES - 1; s++) { load_stage(s, s * 32); CP_COMMIT(); }

    for (int it = 0; it < KITERS; it++) {
        CP_WAIT(TC_STAGES - 2);
        __syncthreads();
        if (it + TC_STAGES - 1 < KITERS)
            load_stage((it + TC_STAGES - 1) % TC_STAGES, (it + TC_STAGES - 1) * 32);
        CP_COMMIT();
        const uint32_t sb = smem_base + (uint32_t)((it % TC_STAGES) * TC_STAGE_BYTES);
        mma_compute_stage<7, 112>(sb, warp_m, warp_n, lane, acc);
    }

    float* outp = z_buf + (size_t)img * 512 * 784 + (size_t)m0 * 784;
    const int part = (img * 7 + blockIdx.x) * 2 + warp_n;
#pragma unroll
    for (int mi = 0; mi < 2; mi++) {
        int r0 = warp_m * 32 + mi * 16 + (lane >> 2);
        float bv0 = biasb[m0 + r0];
        float bv1 = biasb[m0 + r0 + 8];
        float s1a = 0.f, s2a = 0.f, s1b = 0.f, s2b = 0.f;
#pragma unroll
        for (int ni = 0; ni < 7; ni++) {
            int col = n0 + warp_n * 56 + ni * 8 + (lane & 3) * 2;
            float a0 = acc[mi * 7 + ni][0] + bv0;
            float a1 = acc[mi * 7 + ni][1] + bv0;
            float a2 = acc[mi * 7 + ni][2] + bv1;
            float a3 = acc[mi * 7 + ni][3] + bv1;
            s1a += a0 + a1; s2a += a0 * a0 + a1 * a1;
            s1b += a2 + a3; s2b += a2 * a2 + a3 * a3;
            *reinterpret_cast<float2*>(outp + (size_t)r0 * 784 + col) = make_float2(a0, a1);
            *reinterpret_cast<float2*>(outp + (size_t)(r0 + 8) * 784 + col) = make_float2(a2, a3);
        }
        s1a += __shfl_xor_sync(0xffffffff, s1a, 1); s1a += __shfl_xor_sync(0xffffffff, s1a, 2);
        s2a += __shfl_xor_sync(0xffffffff, s2a, 1); s2a += __shfl_xor_sync(0xffffffff, s2a, 2);
        s1b += __shfl_xor_sync(0xffffffff, s1b, 1); s1b += __shfl_xor_sync(0xffffffff, s1b, 2);
        s2b += __shfl_xor_sync(0xffffffff, s2b, 1); s2b += __shfl_xor_sync(0xffffffff, s2b, 2);
        if ((lane & 3) == 0) {
            Zs1[(size_t)part * 512 + m0 + r0]     = s1a;
            Zs2[(size_t)part * 512 + m0 + r0]     = s2a;
            Zs1[(size_t)part * 512 + m0 + r0 + 8] = s1b;
            Zs2[(size_t)part * 512 + m0 + r0 + 8] = s2b;
        }
    }
}

// ---- reduce BN partials ----
__global__ __launch_bounds__(256) void reduce_stats()
{
    const int c = blockIdx.x;
    float s1 = 0.f, s2 = 0.f;
    for (int p = threadIdx.x; p < 896; p += 256) {
        s1 += Zs1[(size_t)p * 512 + c];
        s2 += Zs2[(size_t)p * 512 + c];
    }
    __shared__ float r1[256], r2[256];
    r1[threadIdx.x] = s1; r2[threadIdx.x] = s2;
    __syncthreads();
    for (int off = 128; off > 0; off >>= 1) {
        if (threadIdx.x < off) {
            r1[threadIdx.x] += r1[threadIdx.x + off];
            r2[threadIdx.x] += r2[threadIdx.x + off];
        }
        __syncthreads();
    }
    if (threadIdx.x == 0) { g_stats[c] = r1[0]; g_stats[512 + c] = r2[0]; }
}

// ====================== attention GEMM config: N-tile 64, 2 CTAs/SM ======
static constexpr int SQ_STAGES = 3;
static constexpr int SQ_STAGE_BYTES = 384 * 40 * 2;             // 30720
static constexpr int SQ_SMEM = SQ_STAGES * SQ_STAGE_BYTES;      // 92160

// ---- split-K nt_M: tile 128(i) x 64(j) ----
__global__ __launch_bounds__(256, 2) void mma_nt_M_split()
{
    extern __shared__ __align__(128) __nv_bfloat16 smem[];
    const uint32_t smem_base = smem_to_u32(smem);
    const int tid = threadIdx.x, lane = tid & 31, wid = tid >> 5;
    const int warp_m = wid & 3, warp_n = wid >> 2;
    const int b = blockIdx.z;
    const int sl = blockIdx.y;
    const int i0 = (blockIdx.x >> 2) * 128;
    const int j0 = (blockIdx.x & 3) * 64;
    const int kbase = sl * 224;

    const __nv_bfloat16* A_hi = pp_hi + ((size_t)b * 256 + i0) * 1568 + kbase;
    const __nv_bfloat16* A_lo = pp_lo + ((size_t)b * 256 + i0) * 1568 + kbase;
    const __nv_bfloat16* B_hi = gp_hi + ((size_t)b * 256 + j0) * 1568 + kbase;
    const __nv_bfloat16* B_lo = gp_lo + ((size_t)b * 256 + j0) * 1568 + kbase;

    auto load_stage = [&](int st, int k0) {
        const uint32_t sb = smem_base + (uint32_t)(st * SQ_STAGE_BYTES);
        for (int i = tid; i < 1536; i += 256) {
            int row = i >> 2, kc = i & 3;
            const __nv_bfloat16* src;
            if (row < 128)      src = A_hi + (size_t)row * 1568 + k0 + kc * 8;
            else if (row < 256) src = A_lo + (size_t)(row - 128) * 1568 + k0 + kc * 8;
            else if (row < 320) src = B_hi + (size_t)(row - 256) * 1568 + k0 + kc * 8;
            else                src = B_lo + (size_t)(row - 320) * 1568 + k0 + kc * 8;
            CP_ASYNC16(sb + (uint32_t)((row * 40 + kc * 8) * 2), src);
        }
    };

    float acc[8][4];
#pragma unroll
    for (int q = 0; q < 8; q++)
#pragma unroll
        for (int r = 0; r < 4; r++) acc[q][r] = 0.f;

#pragma unroll
    for (int s = 0; s < SQ_STAGES - 1; s++) { load_stage(s, s * 32); CP_COMMIT(); }

    for (int it = 0; it < 7; it++) {
        CP_WAIT(SQ_STAGES - 2);
        __syncthreads();
        if (it + SQ_STAGES - 1 < 7)
            load_stage((it + SQ_STAGES - 1) % SQ_STAGES, (it + SQ_STAGES - 1) * 32);
        CP_COMMIT();
        const uint32_t sb = smem_base + (uint32_t)((it % SQ_STAGES) * SQ_STAGE_BYTES);
        mma_compute_stage<4, 64>(sb, warp_m, warp_n, lane, acc);
    }

    float* outp = Mpart + ((size_t)(sl * 8 + b)) * 65536;
#pragma unroll
    for (int mi = 0; mi < 2; mi++) {
        int ri = i0 + warp_m * 32 + mi * 16 + (lane >> 2);
#pragma unroll
        for (int ni = 0; ni < 4; ni++) {
            int col = j0 + warp_n * 32 + ni * 8 + (lane & 3) * 2;
            *reinterpret_cast<float2*>(outp + (size_t)ri * 256 + col) =
                make_float2(acc[mi * 4 + ni][0], acc[mi * 4 + ni][1]);
            *reinterpret_cast<float2*>(outp + (size_t)(ri + 8) * 256 + col) =
                make_float2(acc[mi * 4 + ni][2], acc[mi * 4 + ni][3]);
        }
    }
}

// ---- reduce 7 partials, scale, transpose -> Mt bf16 split ----
__global__ __launch_bounds__(256) void reduce_M()
{
    int idx = blockIdx.x * 256 + threadIdx.x;
    int b = idx >> 16, j = (idx >> 8) & 255, i = idx & 255;
    float s = 0.f;
#pragma unroll
    for (int sl = 0; sl < 7; sl++)
        s += Mpart[((size_t)(sl * 8 + b)) * 65536 + (size_t)i * 256 + j];
    split_store(s * (1.0f / 1568.0f), Mt_hi, Mt_lo, (size_t)idx);
}

// ---- tn_y: tile 128(t) x 64(cg), gathered M-tile, coalesced yt stores ----
__global__ __launch_bounds__(256, 2) void mma_tn_y()
{
    extern __shared__ __align__(128) __nv_bfloat16 smem[];
    const uint32_t smem_base = smem_to_u32(smem);
    const int tid = threadIdx.x, lane = tid & 31, wid = tid >> 5;
    const int warp_m = wid & 3, warp_n = wid >> 2;
    const int b = blockIdx.z;
    const int s0 = blockIdx.y * 16;
    const int n0 = blockIdx.x * 64;

    auto load_stage = [&](int st, int k0) {
        const uint32_t sb = smem_base + (uint32_t)(st * SQ_STAGE_BYTES);
        for (int i = tid; i < 1536; i += 256) {
            int row = i >> 2, kc = i & 3;
            const __nv_bfloat16* src;
            if (row < 256) {
                int d = row >> 7, rl = row & 127;
                int t = (rl >> 4) * 784 + s0 + (rl & 15);
                src = (d ? thetat_lo : thetat_hi) + ((size_t)b * 6272 + t) * 256 + k0 + kc * 8;
            } else if (row < 320) {
                src = Mt_hi + ((size_t)b * 256 + n0 + (row - 256)) * 256 + k0 + kc * 8;
            } else {
                src = Mt_lo + ((size_t)b * 256 + n0 + (row - 320)) * 256 + k0 + kc * 8;
            }
            CP_ASYNC16(sb + (uint32_t)((row * 40 + kc * 8) * 2), src);
        }
    };

    float acc[8][4];
#pragma unroll
    for (int q = 0; q < 8; q++)
#pragma unroll
        for (int r = 0; r < 4; r++) acc[q][r] = 0.f;

#pragma unroll
    for (int s = 0; s < SQ_STAGES - 1; s++) { load_stage(s, s * 32); CP_COMMIT(); }

    for (int it = 0; it < 8; it++) {
        CP_WAIT(SQ_STAGES - 2);
        __syncthreads();
        if (it + SQ_STAGES - 1 < 8)
            load_stage((it + SQ_STAGES - 1) % SQ_STAGES, (it + SQ_STAGES - 1) * 32);
        CP_COMMIT();
        const uint32_t sb = smem_base + (uint32_t)((it % SQ_STAGES) * SQ_STAGE_BYTES);
        mma_compute_stage<4, 64>(sb, warp_m, warp_n, lane, acc);
    }
    __syncthreads();

    // stage to smem fp32 [128 rows (tq,si)][pitch 65 cols (cg)]
    float* smf = reinterpret_cast<float*>(smem);
#pragma unroll
    for (int mi = 0; mi < 2; mi++) {
        int r0 = warp_m * 32 + mi * 16 + (lane >> 2);
#pragma unroll
        for (int ni = 0; ni < 4; ni++) {
            int col = warp_n * 32 + ni * 8 + (lane & 3) * 2;
            smf[r0 * 65 + col]           = acc[mi * 4 + ni][0];
            smf[r0 * 65 + col + 1]       = acc[mi * 4 + ni][1];
            smf[(r0 + 8) * 65 + col]     = acc[mi * 4 + ni][2];
            smf[(r0 + 8) * 65 + col + 1] = acc[mi * 4 + ni][3];
        }
    }
    __syncthreads();

    // coalesced store: yt[img][s0+si][c0..c0+7]
    for (int v = tid; v < 1024; v += 256) {
        int kk = v & 31;
        int si = (v >> 5) & 15;
        int ig = v >> 9;
        int col = ig * 32 + kk;
        int cg = n0 + col;
        int img = 8 * b + (cg >> 5);
        int c0 = (cg & 31) * 8;
        __nv_bfloat16 hv[8], lv[8];
#pragma unroll
        for (int tq = 0; tq < 8; tq++) {
            float xv = smf[(tq * 16 + si) * 65 + col];
            __nv_bfloat16 h = __float2bfloat16(xv);
            hv[tq] = h;
            lv[tq] = __float2bfloat16(xv - __bfloat162float(h));
        }
        size_t dst = ((size_t)img * 784 + s0 + si) * 256 + c0;
        *reinterpret_cast<uint4*>(yt_hi + dst) = *reinterpret_cast<uint4*>(hv);
        *reinterpret_cast<uint4*>(yt_lo + dst) = *reinterpret_cast<uint4*>(lv);
    }
}

// ====================== BN apply + residual ======================
__global__ __launch_bounds__(256) void bn_res(
    const float* __restrict__ x,
    const float* __restrict__ gamma, const float* __restrict__ beta,
    float* __restrict__ out)
{
    const int i4 = blockIdx.x * 256 + threadIdx.x;
    const int c = (i4 / 196) & 511;
    const float inv_cnt = 1.0f / 50176.0f;
    float mean = g_stats[c] * inv_cnt;
    float var  = g_stats[512 + c] * inv_cnt - mean * mean;
    float sc = gamma[c] * rsqrtf(var + 1e-5f);
    float sh = beta[c] - mean * sc;
    float4 zv = reinterpret_cast<const float4*>(z_buf)[i4];
    float4 xv = reinterpret_cast<const float4*>(x)[i4];
    float4 o;
    o.x = zv.x * sc + sh + xv.x;
    o.y = zv.y * sc + sh + xv.y;
    o.z = zv.z * sc + sh + xv.z;
    o.w = zv.w * sc + sh + xv.w;
    reinterpret_cast<float4*>(out)[i4] = o;
}

// ====================== launcher ======================
extern "C" void kernel_launch(void* const* d_in, const int* in_sizes, int n_in,
                              void* d_out, int out_size)
{
    const float* x     = (const float*)d_in[0];
    const float* wg    = (const float*)d_in[1];
    const float* bg    = (const float*)d_in[2];
    const float* wth   = (const float*)d_in[3];
    const float* bth   = (const float*)d_in[4];
    const float* wph   = (const float*)d_in[5];
    const float* bph   = (const float*)d_in[6];
    const float* wW    = (const float*)d_in[7];
    const float* bW    = (const float*)d_in[8];
    const float* gamma = (const float*)d_in[9];
    const float* beta  = (const float*)d_in[10];
    float* out = (float*)d_out;

    cudaFuncSetAttribute(proj_gemm_mma,
                         cudaFuncAttributeMaxDynamicSharedMemorySize, TC_SMEM);
    cudaFuncSetAttribute(mma_z_gemm,
                         cudaFuncAttributeMaxDynamicSharedMemorySize, TC_SMEM);
    cudaFuncSetAttribute(mma_nt_M_split,
                         cudaFuncAttributeMaxDynamicSharedMemorySize, SQ_SMEM);
    cudaFuncSetAttribute(mma_tn_y,
                         cudaFuncAttributeMaxDynamicSharedMemorySize, SQ_SMEM);

    split_w_kernel<<<2048, 256>>>(wth, wg, wph, wW);
    split_x_kernel<<<dim3(49, 32, 64), dim3(16, 16)>>>(x);
    init_stats<<<1, 1024>>>();                       // proj at profiled slot

    proj_gemm_mma<<<dim3(7, 6, 64), 256, TC_SMEM>>>(bth, bg, bph);

    mma_nt_M_split<<<dim3(8, 7, 8), 256, SQ_SMEM>>>();
    reduce_M<<<2048, 256>>>();
    mma_tn_y<<<dim3(4, 49, 8), 256, SQ_SMEM>>>();

    mma_z_gemm<<<dim3(7, 4, 64), 256, TC_SMEM>>>(bW);
    reduce_stats<<<512, 256>>>();

    bn_res<<<25088, 256>>>(x, gamma, beta, out);
}

// round 16
// speedup vs baseline: 1.1089x; 1.0747x over previous
#include <cuda_runtime.h>
#include <cuda_bf16.h>
#include <cstdint>

// ====================== mma.sync helpers ======================
__device__ __forceinline__ uint32_t smem_to_u32(const void* smem_ptr) {
    uint32_t addr;
    asm("{ .reg .u64 tmp; cvta.to.shared.u64 tmp, %1; cvt.u32.u64 %0, tmp; }"
        : "=r"(addr) : "l"(smem_ptr));
    return addr;
}
__device__ __forceinline__ void ldsm_x4(uint32_t* r, uint32_t addr) {
    asm volatile("ldmatrix.sync.aligned.m8n8.x4.shared.b16 {%0,%1,%2,%3}, [%4];"
        : "=r"(r[0]), "=r"(r[1]), "=r"(r[2]), "=r"(r[3]) : "r"(addr));
}
__device__ __forceinline__ void ldsm_x2(uint32_t* r, uint32_t addr) {
    asm volatile("ldmatrix.sync.aligned.m8n8.x2.shared.b16 {%0,%1}, [%2];"
        : "=r"(r[0]), "=r"(r[1]) : "r"(addr));
}
__device__ __forceinline__ void mma_16816(float* c, const uint32_t* a, const uint32_t* b) {
    asm volatile("mma.sync.aligned.m16n8k16.row.col.f32.bf16.bf16.f32 "
        "{%0,%1,%2,%3}, {%4,%5,%6,%7}, {%8,%9}, {%0,%1,%2,%3};"
        : "+f"(c[0]), "+f"(c[1]), "+f"(c[2]), "+f"(c[3])
        : "r"(a[0]), "r"(a[1]), "r"(a[2]), "r"(a[3]), "r"(b[0]), "r"(b[1]));
}
#define CP_ASYNC16(dst, src) \
    asm volatile("cp.async.cg.shared.global [%0], [%1], 16;" :: "r"(dst), "l"(src))
#define CP_COMMIT() asm volatile("cp.async.commit_group;" ::: "memory")
#define CP_WAIT(n)  asm volatile("cp.async.wait_group %0;" :: "n"(n) : "memory")

// ---------- 256-thread compute stage: A rows [0,256), B at 256+d*BD. NF frags/warp ----
template <int NF, int BD>
__device__ __forceinline__ void mma_compute_stage(uint32_t sb, int warp_m, int warp_n,
                                                  int lane, float (*acc)[4])
{
    const int a_row = lane & 15, a_kh = lane >> 4;
#pragma unroll
    for (int ks = 0; ks < 2; ks++) {
        uint32_t af[2][2][4];
#pragma unroll
        for (int d = 0; d < 2; d++)
#pragma unroll
            for (int mi = 0; mi < 2; mi++) {
                int r = d * 128 + warp_m * 32 + mi * 16 + a_row;
                int c = ks * 16 + a_kh * 8;
                ldsm_x4(af[d][mi], sb + (uint32_t)((r * 40 + c) * 2));
            }
        uint32_t bq[2][(NF + 1) / 2][4];
#pragma unroll
        for (int d = 0; d < 2; d++) {
#pragma unroll
            for (int np = 0; np < NF / 2; np++) {
                int r = 256 + d * BD + warp_n * (NF * 8) + np * 16 + (lane & 15);
                int c = ks * 16 + (lane >> 4) * 8;
                ldsm_x4(bq[d][np], sb + (uint32_t)((r * 40 + c) * 2));
            }
            if (NF & 1) {
                int r = 256 + d * BD + warp_n * (NF * 8) + (NF - 1) * 8 + (lane & 7);
                int c = ks * 16 + ((lane >> 3) & 1) * 8;
                ldsm_x2(bq[d][NF / 2], sb + (uint32_t)((r * 40 + c) * 2));
            }
        }
#pragma unroll
        for (int mi = 0; mi < 2; mi++)
#pragma unroll
            for (int ni = 0; ni < NF; ni++) {
                uint32_t fh[2], fl[2];
                if ((NF & 1) && ni == NF - 1) {
                    fh[0] = bq[0][NF / 2][0]; fh[1] = bq[0][NF / 2][1];
                    fl[0] = bq[1][NF / 2][0]; fl[1] = bq[1][NF / 2][1];
                } else {
                    fh[0] = bq[0][ni >> 1][ni & 1]; fh[1] = bq[0][ni >> 1][(ni & 1) + 2];
                    fl[0] = bq[1][ni >> 1][ni & 1]; fl[1] = bq[1][ni >> 1][(ni & 1) + 2];
                }
                mma_16816(acc[mi * NF + ni], af[0][mi], fh);
                mma_16816(acc[mi * NF + ni], af[0][mi], fl);
                mma_16816(acc[mi * NF + ni], af[1][mi], fh);
            }
    }
}

// ====================== static scratch ======================
__device__ float z_buf  [64 * 512 * 784];
__device__ float g_stats[1024];
__device__ float Mpart  [7 * 8 * 256 * 256];
__device__ float Zs1    [896 * 512];
__device__ float Zs2    [896 * 512];

__device__ __nv_bfloat16 wcat_hi[768 * 512], wcat_lo[768 * 512];
__device__ __nv_bfloat16 wW_hi [512 * 256],  wW_lo [512 * 256];
__device__ __nv_bfloat16 xt_hi [64 * 784 * 512], xt_lo[64 * 784 * 512];
__device__ __nv_bfloat16 thetat_hi[8 * 6272 * 256], thetat_lo[8 * 6272 * 256];
__device__ __nv_bfloat16 yt_hi [64 * 784 * 256], yt_lo[64 * 784 * 256];
__device__ __nv_bfloat16 gp_hi [8 * 256 * 1568], gp_lo[8 * 256 * 1568];   // p = sp*8+u
__device__ __nv_bfloat16 pp_hi [8 * 256 * 1568], pp_lo[8 * 256 * 1568];
__device__ __nv_bfloat16 Mt_hi [8 * 256 * 256],  Mt_lo[8 * 256 * 256];

__device__ __forceinline__ void split_store(float v, __nv_bfloat16* hi, __nv_bfloat16* lo,
                                            size_t idx) {
    __nv_bfloat16 h = __float2bfloat16(v);
    hi[idx] = h;
    lo[idx] = __float2bfloat16(v - __bfloat162float(h));
}

// ====================== split/convert kernels ======================
__global__ __launch_bounds__(256) void split_w_kernel(
    const float* __restrict__ wth, const float* __restrict__ wg,
    const float* __restrict__ wph, const float* __restrict__ wW)
{
    int i = blockIdx.x * 256 + threadIdx.x;
    if (i < 393216) {
        int r = i >> 9, k = i & 511;
        const float* w = (r < 256) ? wth : (r < 512) ? wg : wph;
        split_store(w[(r & 255) * 512 + k], wcat_hi, wcat_lo, i);
    } else {
        int j = i - 393216;
        split_store(wW[j], wW_hi, wW_lo, j);
    }
}

// x [img][512][784] -> xt [img][784][512] bf16 hi/lo, vectorized uint4 stores.
// Tile: 64 channels x 28 spatial. grid (28, 8, 64), 256 threads.
__global__ __launch_bounds__(256) void split_x_kernel(const float* __restrict__ x)
{
    __shared__ float t[64][29];
    const int img = blockIdx.z;
    const int c0 = blockIdx.y * 64, s0 = blockIdx.x * 28;
    const int tid = threadIdx.x;

    // read: 64 rows x 28 floats, coalesced over s
    const float* src = x + ((size_t)img * 512 + c0) * 784 + s0;
#pragma unroll
    for (int k = 0; k < 7; k++) {
        int i = tid + k * 256;          // 0..1791
        int r = i / 28, col = i - r * 28;
        t[r][col] = src[(size_t)r * 784 + col];
    }
    __syncthreads();

    // write: 224 threads, each 8 consecutive channels for one spatial pos
    if (tid < 224) {
        int sl = tid >> 3;              // 0..27
        int cg = (tid & 7) * 8;         // 0..56
        __nv_bfloat16 hv[8], lv[8];
#pragma unroll
        for (int q = 0; q < 8; q++) {
            float v = t[cg + q][sl];
            __nv_bfloat16 h = __float2bfloat16(v);
            hv[q] = h;
            lv[q] = __float2bfloat16(v - __bfloat162float(h));
        }
        size_t dst = ((size_t)img * 784 + s0 + sl) * 512 + c0 + cg;
        *reinterpret_cast<uint4*>(xt_hi + dst) = *reinterpret_cast<uint4*>(hv);
        *reinterpret_cast<uint4*>(xt_lo + dst) = *reinterpret_cast<uint4*>(lv);
    }
}

__global__ void init_stats()
{
    if (blockIdx.x == 0 && threadIdx.x < 1024) g_stats[threadIdx.x] = 0.f;
}

// ====================== conv GEMM config: 256 thr, 3 stages, 2 CTAs/SM ======
static constexpr int TC_STAGES = 3;
static constexpr int TC_STAGE_BYTES = 480 * 40 * 2;           // 38400
static constexpr int TC_SMEM = TC_STAGES * TC_STAGE_BYTES;    // 115200

// ====================== projection GEMM (theta|g|phi) ======================
__global__ __launch_bounds__(256, 2) void proj_gemm_mma(
    const float* __restrict__ bth, const float* __restrict__ bg,
    const float* __restrict__ bph)
{
    constexpr int KDIM = 512;
    constexpr int KITERS = 16;
    extern __shared__ __align__(128) __nv_bfloat16 smem[];
    const uint32_t smem_base = smem_to_u32(smem);

    const int tid = threadIdx.x;
    const int lane = tid & 31;
    const int wid = tid >> 5;
    const int warp_m = wid & 3;
    const int warp_n = wid >> 2;
    const int img = blockIdx.z;
    const int m0 = blockIdx.y * 128;
    const int n0 = blockIdx.x * 112;

    const __nv_bfloat16* A_hi = wcat_hi + (size_t)m0 * KDIM;
    const __nv_bfloat16* A_lo = wcat_lo + (size_t)m0 * KDIM;
    const __nv_bfloat16* B_hi = xt_hi + ((size_t)img * 784 + n0) * KDIM;
    const __nv_bfloat16* B_lo = xt_lo + ((size_t)img * 784 + n0) * KDIM;

    auto load_stage = [&](int st, int k0) {
        const uint32_t sb = smem_base + (uint32_t)(st * TC_STAGE_BYTES);
        for (int i = tid; i < 1920; i += 256) {
            int row, kc;
            const __nv_bfloat16* src;
            int dst_row;
            if (i < 1024) {
                int d = i >> 9, j = i & 511;
                row = j >> 2; kc = j & 3;
                src = (d ? A_lo : A_hi) + (size_t)row * KDIM + k0 + kc * 8;
                dst_row = d * 128 + row;
            } else {
                int j = i - 1024;
                int d = (j >= 448); if (d) j -= 448;
                row = j >> 2; kc = j & 3;
                src = (d ? B_lo : B_hi) + (size_t)row * KDIM + k0 + kc * 8;
                dst_row = 256 + d * 112 + row;
            }
            uint32_t dst = sb + (uint32_t)((dst_row * 40 + kc * 8) * 2);
            CP_ASYNC16(dst, src);
        }
    };

    float acc[14][4];
#pragma unroll
    for (int q = 0; q < 14; q++)
#pragma unroll
        for (int r = 0; r < 4; r++) acc[q][r] = 0.f;

#pragma unroll
    for (int s = 0; s < TC_STAGES - 1; s++) { load_stage(s, s * 32); CP_COMMIT(); }

    for (int it = 0; it < KITERS; it++) {
        CP_WAIT(TC_STAGES - 2);
        __syncthreads();
        if (it + TC_STAGES - 1 < KITERS)
            load_stage((it + TC_STAGES - 1) % TC_STAGES, (it + TC_STAGES - 1) * 32);
        CP_COMMIT();
        const uint32_t sb = smem_base + (uint32_t)((it % TC_STAGES) * TC_STAGE_BYTES);
        mma_compute_stage<7, 112>(sb, warp_m, warp_n, lane, acc);
    }
    __syncthreads();

    // ---- stage C + bias into SMEM fp32 [128 ch][pitch 113 spatial] ----
    const int region = m0 >> 8;             // 0 theta, 1 g, 2 phi
    const int mloc = m0 & 255;
    const float* bias = (region == 0) ? bth : (region == 1) ? bg : bph;
    float* smf = reinterpret_cast<float*>(smem);

#pragma unroll
    for (int mi = 0; mi < 2; mi++) {
        int r0 = warp_m * 32 + mi * 16 + (lane >> 2);
        float bv0 = bias[mloc + r0];
        float bv1 = bias[mloc + r0 + 8];
#pragma unroll
        for (int ni = 0; ni < 7; ni++) {
            int col = warp_n * 56 + ni * 8 + (lane & 3) * 2;
            smf[r0 * 113 + col]           = acc[mi * 7 + ni][0] + bv0;
            smf[r0 * 113 + col + 1]       = acc[mi * 7 + ni][1] + bv0;
            smf[(r0 + 8) * 113 + col]     = acc[mi * 7 + ni][2] + bv1;
            smf[(r0 + 8) * 113 + col + 1] = acc[mi * 7 + ni][3] + bv1;
        }
    }
    __syncthreads();

    const int b = img >> 3, r = img & 7;
    const int cibase = r * 32 + (mloc >> 3);   // multiple of 16

    if (region == 0) {
        // theta -> thetat[b][t][ci]: 16 consecutive ci per item, uint4 stores
        for (int item = tid; item < 896; item += 256) {
            int sl = item >> 3, u = item & 7;
            int t = u * 784 + n0 + sl;
            size_t dstb = ((size_t)b * 6272 + t) * 256 + cibase;
            __nv_bfloat16 hv[16], lv[16];
#pragma unroll
            for (int q = 0; q < 16; q++) {
                float v = smf[(q * 8 + u) * 113 + sl];
                __nv_bfloat16 h = __float2bfloat16(v);
                hv[q] = h;
                lv[q] = __float2bfloat16(v - __bfloat162float(h));
            }
            *reinterpret_cast<uint4*>(thetat_hi + dstb)     = reinterpret_cast<uint4*>(hv)[0];
            *reinterpret_cast<uint4*>(thetat_hi + dstb + 8) = reinterpret_cast<uint4*>(hv)[1];
            *reinterpret_cast<uint4*>(thetat_lo + dstb)     = reinterpret_cast<uint4*>(lv)[0];
            *reinterpret_cast<uint4*>(thetat_lo + dstb + 8) = reinterpret_cast<uint4*>(lv)[1];
        }
    } else {
        // g/phi: 2x2 pool -> [b][ci][p], ci = cibase + (cc>>3), p = sp*8 + (cc&7)
        __nv_bfloat16* hi = (region == 1) ? gp_hi : pp_hi;
        __nv_bfloat16* lo = (region == 1) ? gp_lo : pp_lo;
        {
            int cc = tid & 127, pr = tid >> 7;
            int ci = cibase + (cc >> 3);
            int u = cc & 7;
            size_t base = ((size_t)b * 256 + ci) * 1568 + (size_t)u;
            int spbase = (2 * blockIdx.x + pr) * 14;
#pragma unroll
            for (int pc = 0; pc < 14; pc++) {
                const float* p = &smf[cc * 113 + pr * 56 + pc * 2];
                float v = fmaxf(fmaxf(p[0], p[1]), fmaxf(p[28], p[29]));
                split_store(v, hi, lo, base + (size_t)(spbase + pc) * 8);
            }
        }
    }
}

// ====================== z GEMM + fused BN partial stats ======================
__global__ __launch_bounds__(256, 2) void mma_z_gemm(const float* __restrict__ biasb)
{
    constexpr int KDIM = 256;
    constexpr int KITERS = 8;
    extern __shared__ __align__(128) __nv_bfloat16 smem[];
    const uint32_t smem_base = smem_to_u32(smem);

    const int tid = threadIdx.x;
    const int lane = tid & 31;
    const int wid = tid >> 5;
    const int warp_m = wid & 3;
    const int warp_n = wid >> 2;
    const int img = blockIdx.z;
    const int m0 = blockIdx.y * 128;
    const int n0 = blockIdx.x * 112;

    const __nv_bfloat16* A_hi = wW_hi + (size_t)m0 * KDIM;
    const __nv_bfloat16* A_lo = wW_lo + (size_t)m0 * KDIM;
    const __nv_bfloat16* B_hi = yt_hi + ((size_t)img * 784 + n0) * KDIM;
    const __nv_bfloat16* B_lo = yt_lo + ((size_t)img * 784 + n0) * KDIM;

    auto load_stage = [&](int st, int k0) {
        const uint32_t sb = smem_base + (uint32_t)(st * TC_STAGE_BYTES);
        for (int i = tid; i < 1920; i += 256) {
            int row, kc;
            const __nv_bfloat16* src;
            int dst_row;
            if (i < 1024) {
                int d = i >> 9, j = i & 511;
                row = j >> 2; kc = j & 3;
                src = (d ? A_lo : A_hi) + (size_t)row * KDIM + k0 + kc * 8;
                dst_row = d * 128 + row;
            } else {
                int j = i - 1024;
                int d = (j >= 448); if (d) j -= 448;
                row = j >> 2; kc = j & 3;
                src = (d ? B_lo : B_hi) + (size_t)row * KDIM + k0 + kc * 8;
                dst_row = 256 + d * 112 + row;
            }
            uint32_t dst = sb + (uint32_t)((dst_row * 40 + kc * 8) * 2);
            CP_ASYNC16(dst, src);
        }
    };

    float acc[14][4];
#pragma unroll
    for (int q = 0; q < 14; q++)
#pragma unroll
        for (int r = 0; r < 4; r++) acc[q][r] = 0.f;

#pragma unroll
    for (int s = 0; s < TC_STAGES - 1; s++) { load_stage(s, s * 32); CP_COMMIT(); }

    for (int it = 0; it < KITERS; it++) {
        CP_WAIT(TC_STAGES - 2);
        __syncthreads();
        if (it + TC_STAGES - 1 < KITERS)
            load_stage((it + TC_STAGES - 1) % TC_STAGES, (it + TC_STAGES - 1) * 32);
        CP_COMMIT();
        const uint32_t sb = smem_base + (uint32_t)((it % TC_STAGES) * TC_STAGE_BYTES);
        mma_compute_stage<7, 112>(sb, warp_m, warp_n, lane, acc);
    }

    float* outp = z_buf + (size_t)img * 512 * 784 + (size_t)m0 * 784;
    const int part = (img * 7 + blockIdx.x) * 2 + warp_n;
#pragma unroll
    for (int mi = 0; mi < 2; mi++) {
        int r0 = warp_m * 32 + mi * 16 + (lane >> 2);
        float bv0 = biasb[m0 + r0];
        float bv1 = biasb[m0 + r0 + 8];
        float s1a = 0.f, s2a = 0.f, s1b = 0.f, s2b = 0.f;
#pragma unroll
        for (int ni = 0; ni < 7; ni++) {
            int col = n0 + warp_n * 56 + ni * 8 + (lane & 3) * 2;
            float a0 = acc[mi * 7 + ni][0] + bv0;
            float a1 = acc[mi * 7 + ni][1] + bv0;
            float a2 = acc[mi * 7 + ni][2] + bv1;
            float a3 = acc[mi * 7 + ni][3] + bv1;
            s1a += a0 + a1; s2a += a0 * a0 + a1 * a1;
            s1b += a2 + a3; s2b += a2 * a2 + a3 * a3;
            *reinterpret_cast<float2*>(outp + (size_t)r0 * 784 + col) = make_float2(a0, a1);
            *reinterpret_cast<float2*>(outp + (size_t)(r0 + 8) * 784 + col) = make_float2(a2, a3);
        }
        s1a += __shfl_xor_sync(0xffffffff, s1a, 1); s1a += __shfl_xor_sync(0xffffffff, s1a, 2);
        s2a += __shfl_xor_sync(0xffffffff, s2a, 1); s2a += __shfl_xor_sync(0xffffffff, s2a, 2);
        s1b += __shfl_xor_sync(0xffffffff, s1b, 1); s1b += __shfl_xor_sync(0xffffffff, s1b, 2);
        s2b += __shfl_xor_sync(0xffffffff, s2b, 1); s2b += __shfl_xor_sync(0xffffffff, s2b, 2);
        if ((lane & 3) == 0) {
            Zs1[(size_t)part * 512 + m0 + r0]     = s1a;
            Zs2[(size_t)part * 512 + m0 + r0]     = s2a;
            Zs1[(size_t)part * 512 + m0 + r0 + 8] = s1b;
            Zs2[(size_t)part * 512 + m0 + r0 + 8] = s2b;
        }
    }
}

// ---- reduce BN partials ----
__global__ __launch_bounds__(256) void reduce_stats()
{
    const int c = blockIdx.x;
    float s1 = 0.f, s2 = 0.f;
    for (int p = threadIdx.x; p < 896; p += 256) {
        s1 += Zs1[(size_t)p * 512 + c];
        s2 += Zs2[(size_t)p * 512 + c];
    }
    __shared__ float r1[256], r2[256];
    r1[threadIdx.x] = s1; r2[threadIdx.x] = s2;
    __syncthreads();
    for (int off = 128; off > 0; off >>= 1) {
        if (threadIdx.x < off) {
            r1[threadIdx.x] += r1[threadIdx.x + off];
            r2[threadIdx.x] += r2[threadIdx.x + off];
        }
        __syncthreads();
    }
    if (threadIdx.x == 0) { g_stats[c] = r1[0]; g_stats[512 + c] = r2[0]; }
}

// ====================== attention GEMM config: N-tile 64, 2 CTAs/SM ======
static constexpr int SQ_STAGES = 3;
static constexpr int SQ_STAGE_BYTES = 384 * 40 * 2;             // 30720
static constexpr int SQ_SMEM = SQ_STAGES * SQ_STAGE_BYTES;      // 92160

// ---- split-K nt_M: tile 128(i) x 64(j) ----
__global__ __launch_bounds__(256, 2) void mma_nt_M_split()
{
    extern __shared__ __align__(128) __nv_bfloat16 smem[];
    const uint32_t smem_base = smem_to_u32(smem);
    const int tid = threadIdx.x, lane = tid & 31, wid = tid >> 5;
    const int warp_m = wid & 3, warp_n = wid >> 2;
    const int b = blockIdx.z;
    const int sl = blockIdx.y;
    const int i0 = (blockIdx.x >> 2) * 128;
    const int j0 = (blockIdx.x & 3) * 64;
    const int kbase = sl * 224;

    const __nv_bfloat16* A_hi = pp_hi + ((size_t)b * 256 + i0) * 1568 + kbase;
    const __nv_bfloat16* A_lo = pp_lo + ((size_t)b * 256 + i0) * 1568 + kbase;
    const __nv_bfloat16* B_hi = gp_hi + ((size_t)b * 256 + j0) * 1568 + kbase;
    const __nv_bfloat16* B_lo = gp_lo + ((size_t)b * 256 + j0) * 1568 + kbase;

    auto load_stage = [&](int st, int k0) {
        const uint32_t sb = smem_base + (uint32_t)(st * SQ_STAGE_BYTES);
        for (int i = tid; i < 1536; i += 256) {
            int row = i >> 2, kc = i & 3;
            const __nv_bfloat16* src;
            if (row < 128)      src = A_hi + (size_t)row * 1568 + k0 + kc * 8;
            else if (row < 256) src = A_lo + (size_t)(row - 128) * 1568 + k0 + kc * 8;
            else if (row < 320) src = B_hi + (size_t)(row - 256) * 1568 + k0 + kc * 8;
            else                src = B_lo + (size_t)(row - 320) * 1568 + k0 + kc * 8;
            CP_ASYNC16(sb + (uint32_t)((row * 40 + kc * 8) * 2), src);
        }
    };

    float acc[8][4];
#pragma unroll
    for (int q = 0; q < 8; q++)
#pragma unroll
        for (int r = 0; r < 4; r++) acc[q][r] = 0.f;

#pragma unroll
    for (int s = 0; s < SQ_STAGES - 1; s++) { load_stage(s, s * 32); CP_COMMIT(); }

    for (int it = 0; it < 7; it++) {
        CP_WAIT(SQ_STAGES - 2);
        __syncthreads();
        if (it + SQ_STAGES - 1 < 7)
            load_stage((it + SQ_STAGES - 1) % SQ_STAGES, (it + SQ_STAGES - 1) * 32);
        CP_COMMIT();
        const uint32_t sb = smem_base + (uint32_t)((it % SQ_STAGES) * SQ_STAGE_BYTES);
        mma_compute_stage<4, 64>(sb, warp_m, warp_n, lane, acc);
    }

    float* outp = Mpart + ((size_t)(sl * 8 + b)) * 65536;
#pragma unroll
    for (int mi = 0; mi < 2; mi++) {
        int ri = i0 + warp_m * 32 + mi * 16 + (lane >> 2);
#pragma unroll
        for (int ni = 0; ni < 4; ni++) {
            int col = j0 + warp_n * 32 + ni * 8 + (lane & 3) * 2;
            *reinterpret_cast<float2*>(outp + (size_t)ri * 256 + col) =
                make_float2(acc[mi * 4 + ni][0], acc[mi * 4 + ni][1]);
            *reinterpret_cast<float2*>(outp + (size_t)(ri + 8) * 256 + col) =
                make_float2(acc[mi * 4 + ni][2], acc[mi * 4 + ni][3]);
        }
    }
}

// ---- reduce 7 partials, scale, transpose -> Mt bf16 split ----
__global__ __launch_bounds__(256) void reduce_M()
{
    int idx = blockIdx.x * 256 + threadIdx.x;
    int b = idx >> 16, j = (idx >> 8) & 255, i = idx & 255;
    float s = 0.f;
#pragma unroll
    for (int sl = 0; sl < 7; sl++)
        s += Mpart[((size_t)(sl * 8 + b)) * 65536 + (size_t)i * 256 + j];
    split_store(s * (1.0f / 1568.0f), Mt_hi, Mt_lo, (size_t)idx);
}

// ---- tn_y: tile 128(t) x 64(cg), gathered M-tile, coalesced yt stores ----
__global__ __launch_bounds__(256, 2) void mma_tn_y()
{
    extern __shared__ __align__(128) __nv_bfloat16 smem[];
    const uint32_t smem_base = smem_to_u32(smem);
    const int tid = threadIdx.x, lane = tid & 31, wid = tid >> 5;
    const int warp_m = wid & 3, warp_n = wid >> 2;
    const int b = blockIdx.z;
    const int s0 = blockIdx.y * 16;
    const int n0 = blockIdx.x * 64;

    auto load_stage = [&](int st, int k0) {
        const uint32_t sb = smem_base + (uint32_t)(st * SQ_STAGE_BYTES);
        for (int i = tid; i < 1536; i += 256) {
            int row = i >> 2, kc = i & 3;
            const __nv_bfloat16* src;
            if (row < 256) {
                int d = row >> 7, rl = row & 127;
                int t = (rl >> 4) * 784 + s0 + (rl & 15);
                src = (d ? thetat_lo : thetat_hi) + ((size_t)b * 6272 + t) * 256 + k0 + kc * 8;
            } else if (row < 320) {
                src = Mt_hi + ((size_t)b * 256 + n0 + (row - 256)) * 256 + k0 + kc * 8;
            } else {
                src = Mt_lo + ((size_t)b * 256 + n0 + (row - 320)) * 256 + k0 + kc * 8;
            }
            CP_ASYNC16(sb + (uint32_t)((row * 40 + kc * 8) * 2), src);
        }
    };

    float acc[8][4];
#pragma unroll
    for (int q = 0; q < 8; q++)
#pragma unroll
        for (int r = 0; r < 4; r++) acc[q][r] = 0.f;

#pragma unroll
    for (int s = 0; s < SQ_STAGES - 1; s++) { load_stage(s, s * 32); CP_COMMIT(); }

    for (int it = 0; it < 8; it++) {
        CP_WAIT(SQ_STAGES - 2);
        __syncthreads();
        if (it + SQ_STAGES - 1 < 8)
            load_stage((it + SQ_STAGES - 1) % SQ_STAGES, (it + SQ_STAGES - 1) * 32);
        CP_COMMIT();
        const uint32_t sb = smem_base + (uint32_t)((it % SQ_STAGES) * SQ_STAGE_BYTES);
        mma_compute_stage<4, 64>(sb, warp_m, warp_n, lane, acc);
    }
    __syncthreads();

    // stage to smem fp32 [128 rows (tq,si)][pitch 65 cols (cg)]
    float* smf = reinterpret_cast<float*>(smem);
#pragma unroll
    for (int mi = 0; mi < 2; mi++) {
        int r0 = warp_m * 32 + mi * 16 + (lane >> 2);
#pragma unroll
        for (int ni = 0; ni < 4; ni++) {
            int col = warp_n * 32 + ni * 8 + (lane & 3) * 2;
            smf[r0 * 65 + col]           = acc[mi * 4 + ni][0];
            smf[r0 * 65 + col + 1]       = acc[mi * 4 + ni][1];
            smf[(r0 + 8) * 65 + col]     = acc[mi * 4 + ni][2];
            smf[(r0 + 8) * 65 + col + 1] = acc[mi * 4 + ni][3];
        }
    }
    __syncthreads();

    // coalesced store: yt[img][s0+si][c0..c0+7]
    for (int v = tid; v < 1024; v += 256) {
        int kk = v & 31;
        int si = (v >> 5) & 15;
        int ig = v >> 9;
        int col = ig * 32 + kk;
        int cg = n0 + col;
        int img = 8 * b + (cg >> 5);
        int c0 = (cg & 31) * 8;
        __nv_bfloat16 hv[8], lv[8];
#pragma unroll
        for (int tq = 0; tq < 8; tq++) {
            float xv = smf[(tq * 16 + si) * 65 + col];
            __nv_bfloat16 h = __float2bfloat16(xv);
            hv[tq] = h;
            lv[tq] = __float2bfloat16(xv - __bfloat162float(h));
        }
        size_t dst = ((size_t)img * 784 + s0 + si) * 256 + c0;
        *reinterpret_cast<uint4*>(yt_hi + dst) = *reinterpret_cast<uint4*>(hv);
        *reinterpret_cast<uint4*>(yt_lo + dst) = *reinterpret_cast<uint4*>(lv);
    }
}

// ====================== BN apply + residual ======================
__global__ __launch_bounds__(256) void bn_res(
    const float* __restrict__ x,
    const float* __restrict__ gamma, const float* __restrict__ beta,
    float* __restrict__ out)
{
    const int i4 = blockIdx.x * 256 + threadIdx.x;
    const int c = (i4 / 196) & 511;
    const float inv_cnt = 1.0f / 50176.0f;
    float mean = g_stats[c] * inv_cnt;
    float var  = g_stats[512 + c] * inv_cnt - mean * mean;
    float sc = gamma[c] * rsqrtf(var + 1e-5f);
    float sh = beta[c] - mean * sc;
    float4 zv = reinterpret_cast<const float4*>(z_buf)[i4];
    float4 xv = reinterpret_cast<const float4*>(x)[i4];
    float4 o;
    o.x = zv.x * sc + sh + xv.x;
    o.y = zv.y * sc + sh + xv.y;
    o.z = zv.z * sc + sh + xv.z;
    o.w = zv.w * sc + sh + xv.w;
    reinterpret_cast<float4*>(out)[i4] = o;
}

// ====================== launcher ======================
extern "C" void kernel_launch(void* const* d_in, const int* in_sizes, int n_in,
                              void* d_out, int out_size)
{
    const float* x     = (const float*)d_in[0];
    const float* wg    = (const float*)d_in[1];
    const float* bg    = (const float*)d_in[2];
    const float* wth   = (const float*)d_in[3];
    const float* bth   = (const float*)d_in[4];
    const float* wph   = (const float*)d_in[5];
    const float* bph   = (const float*)d_in[6];
    const float* wW    = (const float*)d_in[7];
    const float* bW    = (const float*)d_in[8];
    const float* gamma = (const float*)d_in[9];
    const float* beta  = (const float*)d_in[10];
    float* out = (float*)d_out;

    cudaFuncSetAttribute(proj_gemm_mma,
                         cudaFuncAttributeMaxDynamicSharedMemorySize, TC_SMEM);
    cudaFuncSetAttribute(mma_z_gemm,
                         cudaFuncAttributeMaxDynamicSharedMemorySize, TC_SMEM);
    cudaFuncSetAttribute(mma_nt_M_split,
                         cudaFuncAttributeMaxDynamicSharedMemorySize, SQ_SMEM);
    cudaFuncSetAttribute(mma_tn_y,
                         cudaFuncAttributeMaxDynamicSharedMemorySize, SQ_SMEM);

    split_w_kernel<<<2048, 256>>>(wth, wg, wph, wW);
    split_x_kernel<<<dim3(28, 8, 64), 256>>>(x);
    init_stats<<<1, 1024>>>();                       // proj at profiled slot

    proj_gemm_mma<<<dim3(7, 6, 64), 256, TC_SMEM>>>(bth, bg, bph);

    mma_nt_M_split<<<dim3(8, 7, 8), 256, SQ_SMEM>>>();
    reduce_M<<<2048, 256>>>();
    mma_tn_y<<<dim3(4, 49, 8), 256, SQ_SMEM>>>();

    mma_z_gemm<<<dim3(7, 4, 64), 256, TC_SMEM>>>(bW);
    reduce_stats<<<512, 256>>>();

    bn_res<<<25088, 256>>>(x, gamma, beta, out);
}